// round 9
// baseline (speedup 1.0000x reference)
#include <cuda_runtime.h>
#include <cuda_bf16.h>
#include <cstdint>

#define N_SAMP 2048
#define DIN    1024
#define DFEAT  2048
#define DIMF   128
#define CC     1000
#define QQ     8
#define NQ     8000
#define NQS    8192      // padded sim_q stride
#define KNEG   1024
#define NCON   3075      // 2047 + 4 + 1024
#define NEGCNT 7992

// output layout (float32, tuple order, row-major flattened)
#define OFF_SIMCON 0ull
#define OFF_LABCON 6297600ull
#define OFF_LOGIT  12595200ull
#define OFF_QUEUE  14643200ull
#define OFF_QPTR   15667200ull

// ---------------- device scratch ----------------
__device__ float g_h   [N_SAMP * DFEAT];
__device__ float g_simq[N_SAMP * NQS];
__device__ float g_feat[N_SAMP * DIMF];
__device__ float g_fpart[4 * N_SAMP * DIMF];
__device__ float g_psum[16 * DFEAT];
__device__ float g_psq [16 * DFEAT];
__device__ float g_mean[DFEAT];
__device__ float g_rstd[DFEAT];
__device__ int   g_win [1024];
__device__ __nv_bfloat16 g_ahi[N_SAMP * DFEAT];   // mid split
__device__ __nv_bfloat16 g_alo[N_SAMP * DFEAT];
__device__ __nv_bfloat16 g_chi[N_SAMP * DFEAT];   // img split, then hn split
__device__ __nv_bfloat16 g_clo[N_SAMP * DFEAT];
__device__ __nv_bfloat16 g_fhi[N_SAMP * DIMF];    // feat split
__device__ __nv_bfloat16 g_flo[N_SAMP * DIMF];
// weight splits (transposed [N][K])
__device__ __nv_bfloat16 g_ehi [DFEAT * DIN];
__device__ __nv_bfloat16 g_elo [DFEAT * DIN];
__device__ __nv_bfloat16 g_w1hi[DFEAT * DFEAT];
__device__ __nv_bfloat16 g_w1lo[DFEAT * DFEAT];
__device__ __nv_bfloat16 g_lnhi[1024 * DFEAT];
__device__ __nv_bfloat16 g_lnlo[1024 * DFEAT];
__device__ __nv_bfloat16 g_w2hi[DIMF * DFEAT];
__device__ __nv_bfloat16 g_w2lo[DIMF * DFEAT];
__device__ __nv_bfloat16 g_qhi [NQS * DIMF];
__device__ __nv_bfloat16 g_qlo [NQS * DIMF];

// ================= helpers =================
__device__ __forceinline__ uint32_t smem_u32(const void* p) {
    uint32_t a;
    asm("{ .reg .u64 t; cvta.to.shared.u64 t, %1; cvt.u32.u64 %0, t; }" : "=r"(a) : "l"(p));
    return a;
}
__device__ __forceinline__ void cpa16(uint32_t s, const void* g) {
    asm volatile("cp.async.cg.shared.global [%0], [%1], 16;" :: "r"(s), "l"(g) : "memory");
}
__device__ __forceinline__ void ldsm4(uint32_t* r, uint32_t addr) {
    asm volatile("ldmatrix.sync.aligned.m8n8.x4.shared.b16 {%0,%1,%2,%3}, [%4];"
                 : "=r"(r[0]), "=r"(r[1]), "=r"(r[2]), "=r"(r[3]) : "r"(addr));
}
__device__ __forceinline__ void mma_bf16(float* c, const uint32_t* a, const uint32_t* b) {
    asm volatile("mma.sync.aligned.m16n8k16.row.col.f32.bf16.bf16.f32 "
                 "{%0,%1,%2,%3}, {%4,%5,%6,%7}, {%8,%9}, {%0,%1,%2,%3};"
                 : "+f"(c[0]), "+f"(c[1]), "+f"(c[2]), "+f"(c[3])
                 : "r"(a[0]), "r"(a[1]), "r"(a[2]), "r"(a[3]), "r"(b[0]), "r"(b[1]));
}
__device__ __forceinline__ void split_bf(float v, __nv_bfloat16& h, __nv_bfloat16& l) {
    h = __float2bfloat16(v);
    l = __float2bfloat16(v - __bfloat162float(h));
}

// ================= split-bf16 MMA GEMM: C[M x Ntile*grid] = A @ B^T =================
// 512 threads, CTA tile 128 x (NI*32), warp tile 32 x (NI*8), BK=32, double-buffered.
// 3-pass split (hi*hi + hi*lo + lo*hi). B fragments via paired ldsm4.
// mode: 0 fp32(+bias), 1 offdiag-compact, 2 bounded cols(+bias), 3 bf16 split out(+bias),
//       4 split-K partial fp32 (offset blockIdx.z)
template<int NI>
__global__ void __launch_bounds__(512, 1) gemm_mma(
    const __nv_bfloat16* __restrict__ Ahi, const __nv_bfloat16* __restrict__ Alo,
    const __nv_bfloat16* __restrict__ Bhi, const __nv_bfloat16* __restrict__ Blo,
    const float* __restrict__ bias, float* __restrict__ C,
    __nv_bfloat16* __restrict__ Ohi, __nv_bfloat16* __restrict__ Olo,
    int K, int Ksub, int ldC, int mode, int nbound)
{
    constexpr uint32_t SA_LO = 10240;              // 128*80
    constexpr uint32_t SB_HI = 20480;
    constexpr uint32_t SB_LO = 20480 + NI * 2560;  // NI*32*80
    constexpr uint32_t STAGE = 20480 + 2 * NI * 2560;

    extern __shared__ __align__(128) char sm[];
    const uint32_t sb = smem_u32(sm);
    const int tid = threadIdx.x, wid = tid >> 5, lane = tid & 31;
    const int rowBase = blockIdx.y * 128, nBase = blockIdx.x * (NI * 32);
    const int kbase = blockIdx.z * Ksub;
    const int nch = Ksub >> 5;

    float acc[2][NI][4];
    #pragma unroll
    for (int i = 0; i < 2; i++)
        #pragma unroll
        for (int j = 0; j < NI; j++)
            #pragma unroll
            for (int q = 0; q < 4; q++) acc[i][j][q] = 0.f;

    // loader: 512 threads, each handles one 16B segment per array slab of 128 rows
    const uint32_t aoff = (tid >> 2) * 80 + (tid & 3) * 16;
    const size_t ga = (size_t)(rowBase + (tid >> 2)) * K + (tid & 3) * 8 + kbase;
    const size_t gb = (size_t)(nBase  + (tid >> 2)) * K + (tid & 3) * 8 + kbase;

#define ISSUE(st, ch) do {                                                            \
        const int k0_ = (ch) << 5;                                                    \
        const uint32_t B0_ = sb + (st) * STAGE;                                       \
        cpa16(B0_ + aoff,         Ahi + ga + k0_);                                    \
        cpa16(B0_ + SA_LO + aoff, Alo + ga + k0_);                                    \
        _Pragma("unroll")                                                             \
        for (int it = 0; it < NI / 4; it++) {                                         \
            cpa16(B0_ + SB_HI + aoff + it * 10240, Bhi + gb + (size_t)(it*128)*K + k0_); \
            cpa16(B0_ + SB_LO + aoff + it * 10240, Blo + gb + (size_t)(it*128)*K + k0_); \
        }                                                                             \
        asm volatile("cp.async.commit_group;" ::: "memory");                          \
    } while (0)

    ISSUE(0, 0);

    const int wm = (wid >> 2) * 32, wn = (wid & 3) * (NI * 8);
    const int arow = lane & 15, ahalf = lane >> 4;
    // B paired-ldsm4 lane mapping: lanes 0-15 -> ni=2p (khalf=(lane>>3)&1),
    // lanes 16-31 -> ni=2p+1
    const int bpr = ((lane >> 4) & 1) * 8 + (lane & 7);
    const int bkh = (lane >> 3) & 1;

    for (int ch = 0; ch < nch; ch++) {
        if (ch + 1 < nch) {
            ISSUE((ch + 1) & 1, ch + 1);
            asm volatile("cp.async.wait_group 1;" ::: "memory");
        } else {
            asm volatile("cp.async.wait_group 0;" ::: "memory");
        }
        __syncthreads();
        const uint32_t base = sb + (ch & 1) * STAGE;

        #pragma unroll
        for (int ks = 0; ks < 2; ks++) {
            uint32_t fahi[2][4], falo[2][4];
            #pragma unroll
            for (int mi = 0; mi < 2; mi++) {
                uint32_t ad = base + (wm + mi * 16 + arow) * 80 + ks * 32 + ahalf * 16;
                ldsm4(fahi[mi], ad);
                ldsm4(falo[mi], ad + SA_LO);
            }
            #pragma unroll
            for (int p = 0; p < NI / 2; p++) {
                uint32_t bd = base + SB_HI + (wn + p * 16 + bpr) * 80 + ks * 32 + bkh * 16;
                uint32_t fbh[4], fbl[4];
                ldsm4(fbh, bd);
                ldsm4(fbl, bd + NI * 2560);
                #pragma unroll
                for (int mi = 0; mi < 2; mi++) {
                    mma_bf16(acc[mi][2*p],   fahi[mi], fbh);
                    mma_bf16(acc[mi][2*p+1], fahi[mi], fbh + 2);
                }
                #pragma unroll
                for (int mi = 0; mi < 2; mi++) {
                    mma_bf16(acc[mi][2*p],   fahi[mi], fbl);
                    mma_bf16(acc[mi][2*p+1], fahi[mi], fbl + 2);
                }
                #pragma unroll
                for (int mi = 0; mi < 2; mi++) {
                    mma_bf16(acc[mi][2*p],   falo[mi], fbh);
                    mma_bf16(acc[mi][2*p+1], falo[mi], fbh + 2);
                }
            }
        }
        __syncthreads();
    }
#undef ISSUE

    // ---- epilogue ----
    const int qrow = lane >> 2, qcol = (lane & 3) * 2;
    #pragma unroll
    for (int mi = 0; mi < 2; mi++) {
        #pragma unroll
        for (int hh = 0; hh < 2; hh++) {
            const int r = rowBase + wm + mi * 16 + qrow + hh * 8;
            #pragma unroll
            for (int ni = 0; ni < NI; ni++) {
                const int c = nBase + wn + ni * 8 + qcol;
                float v0 = acc[mi][ni][hh * 2 + 0];
                float v1 = acc[mi][ni][hh * 2 + 1];
                if (mode == 0) {
                    if (bias) { v0 += bias[c]; v1 += bias[c + 1]; }
                    *(float2*)(C + (size_t)r * ldC + c) = make_float2(v0, v1);
                } else if (mode == 1) {
                    if (c != r)     C[(size_t)r * ldC + c     - (c     > r ? 1 : 0)] = v0;
                    if (c + 1 != r) C[(size_t)r * ldC + c + 1 - (c + 1 > r ? 1 : 0)] = v1;
                } else if (mode == 2) {
                    if (c < nbound)     C[(size_t)r * ldC + c]     = v0 + bias[c];
                    if (c + 1 < nbound) C[(size_t)r * ldC + c + 1] = v1 + bias[c + 1];
                } else if (mode == 3) {
                    v0 += bias[c]; v1 += bias[c + 1];
                    __nv_bfloat16 h0, l0, h1, l1;
                    split_bf(v0, h0, l0); split_bf(v1, h1, l1);
                    *(__nv_bfloat162*)(Ohi + (size_t)r * ldC + c) = __nv_bfloat162(h0, h1);
                    *(__nv_bfloat162*)(Olo + (size_t)r * ldC + c) = __nv_bfloat162(l0, l1);
                } else {
                    float* Cz = C + (size_t)blockIdx.z * N_SAMP * DIMF;
                    *(float2*)(Cz + (size_t)r * ldC + c) = make_float2(v0, v1);
                }
            }
        }
    }
}

// ============ all weight conversions in one kernel (transpose + split, bf162 stores) ============
__global__ void conv_all(const float* __restrict__ encW, const float* __restrict__ W1,
                         const float* __restrict__ linW, const float* __restrict__ W2,
                         const float* __restrict__ ql,
                         __nv_bfloat16* ehi, __nv_bfloat16* elo,
                         __nv_bfloat16* w1hi, __nv_bfloat16* w1lo,
                         __nv_bfloat16* lnhi, __nv_bfloat16* lnlo,
                         __nv_bfloat16* w2hi, __nv_bfloat16* w2lo,
                         __nv_bfloat16* qhi,  __nv_bfloat16* qlo)
{
    __shared__ float ts[32][33];
    const int b = blockIdx.x;
    const float* W; __nv_bfloat16 *hi, *lo; int K, N, nx, id;
    if (b < 2048)      { W = encW; hi = ehi;  lo = elo;  K = 1024; N = 2048; nx = 64;  id = b; }
    else if (b < 6144) { W = W1;   hi = w1hi; lo = w1lo; K = 2048; N = 2048; nx = 64;  id = b - 2048; }
    else if (b < 8192) { W = linW; hi = lnhi; lo = lnlo; K = 2048; N = 1000; nx = 32;  id = b - 6144; }
    else if (b < 8448) { W = W2;   hi = w2hi; lo = w2lo; K = 2048; N = 128;  nx = 4;   id = b - 8192; }
    else               { W = ql;   hi = qhi;  lo = qlo;  K = 128;  N = 8000; nx = 256; id = b - 8448; }
    const int nb = (id % nx) * 32, kb = (id / nx) * 32;

    const int c = threadIdx.x & 31, r8 = threadIdx.x >> 5;
    #pragma unroll
    for (int rr = r8; rr < 32; rr += 8) {
        int n = nb + c;
        ts[rr][c] = (n < N) ? W[(size_t)(kb + rr) * N + n] : 0.f;
    }
    __syncthreads();
    const int c16 = threadIdx.x & 15, rh = threadIdx.x >> 4;
    #pragma unroll
    for (int rr = rh; rr < 32; rr += 16) {
        float v0 = ts[2 * c16][rr], v1 = ts[2 * c16 + 1][rr];
        __nv_bfloat16 h0, l0, h1, l1;
        split_bf(v0, h0, l0); split_bf(v1, h1, l1);
        size_t o = (size_t)(nb + rr) * K + kb;
        ((__nv_bfloat162*)(hi + o))[c16] = __nv_bfloat162(h0, h1);
        ((__nv_bfloat162*)(lo + o))[c16] = __nv_bfloat162(l0, l1);
    }
}

// ============ plain split (vectorized): fp32 row-major -> bf16 hi/lo ============
__global__ void conv_plain(const float* __restrict__ X, __nv_bfloat16* __restrict__ hi,
                           __nv_bfloat16* __restrict__ lo, int n4)
{
    int i = blockIdx.x * 256 + threadIdx.x;
    if (i >= n4) return;
    float4 v = ((const float4*)X)[i];
    __nv_bfloat16 h0,l0,h1,l1,h2,l2,h3,l3;
    split_bf(v.x,h0,l0); split_bf(v.y,h1,l1); split_bf(v.z,h2,l2); split_bf(v.w,h3,l3);
    ((__nv_bfloat162*)hi)[i*2]   = __nv_bfloat162(h0,h1);
    ((__nv_bfloat162*)hi)[i*2+1] = __nv_bfloat162(h2,h3);
    ((__nv_bfloat162*)lo)[i*2]   = __nv_bfloat162(l0,l1);
    ((__nv_bfloat162*)lo)[i*2+1] = __nv_bfloat162(l2,l3);
}

// ---------------- batchnorm (deterministic two-stage) ----------------
__global__ void bn_partial(const float* __restrict__ h)
{
    int col = blockIdx.x * 256 + threadIdx.x;
    int r0 = blockIdx.y * 128;
    float s = 0.f, sq = 0.f;
    for (int i = 0; i < 128; i++) {
        float v = h[(size_t)(r0 + i) * DFEAT + col];
        s += v; sq += v * v;
    }
    g_psum[blockIdx.y * DFEAT + col] = s;
    g_psq [blockIdx.y * DFEAT + col] = sq;
}

__global__ void bn_final()
{
    int col = blockIdx.x * 256 + threadIdx.x;
    float s = 0.f, sq = 0.f;
    for (int i = 0; i < 16; i++) { s += g_psum[i * DFEAT + col]; sq += g_psq[i * DFEAT + col]; }
    float mean = s * (1.f / N_SAMP);
    float var  = sq * (1.f / N_SAMP) - mean * mean;
    g_mean[col] = mean;
    g_rstd[col] = rsqrtf(var + 1e-5f);
}

__global__ void bn_apply(const float* __restrict__ h, const float* __restrict__ gamma,
                         const float* __restrict__ beta,
                         __nv_bfloat16* __restrict__ hi, __nv_bfloat16* __restrict__ lo)
{
    int idx = blockIdx.x * 256 + threadIdx.x;
    int col = (idx * 2) & (DFEAT - 1);
    float2 v2 = ((const float2*)h)[idx];
    float v0 = (v2.x - g_mean[col])   * g_rstd[col]   * gamma[col]   + beta[col];
    float v1 = (v2.y - g_mean[col+1]) * g_rstd[col+1] * gamma[col+1] + beta[col+1];
    v0 = v0 > 0.f ? v0 : 0.f;
    v1 = v1 > 0.f ? v1 : 0.f;
    __nv_bfloat16 h0,l0,h1,l1;
    split_bf(v0,h0,l0); split_bf(v1,h1,l1);
    ((__nv_bfloat162*)hi)[idx] = __nv_bfloat162(h0,h1);
    ((__nv_bfloat162*)lo)[idx] = __nv_bfloat162(l0,l1);
}

// ---------------- feat finalize: reduce split-K partials + bias + L2 norm + split ----------------
__global__ void feat_fix(const float* __restrict__ part, const float* __restrict__ b2,
                         float* __restrict__ feat,
                         __nv_bfloat16* __restrict__ fhi, __nv_bfloat16* __restrict__ flo)
{
    int w = threadIdx.x >> 5, lane = threadIdx.x & 31;
    int row = blockIdx.x * 8 + w;
    float4 v = make_float4(0.f, 0.f, 0.f, 0.f);
    #pragma unroll
    for (int p = 0; p < 4; p++) {
        float4 t = *(const float4*)(part + (size_t)p * N_SAMP * DIMF + (size_t)row * DIMF + lane * 4);
        v.x += t.x; v.y += t.y; v.z += t.z; v.w += t.w;
    }
    float4 b = *(const float4*)(b2 + lane * 4);
    v.x += b.x; v.y += b.y; v.z += b.z; v.w += b.w;
    float ss = v.x * v.x + v.y * v.y + v.z * v.z + v.w * v.w;
    #pragma unroll
    for (int o = 16; o; o >>= 1) ss += __shfl_xor_sync(0xffffffffu, ss, o);
    float r = rsqrtf(ss);
    v.x *= r; v.y *= r; v.z *= r; v.w *= r;
    *(float4*)(feat + (size_t)row * DIMF + lane * 4) = v;
    __nv_bfloat16 h0,l0,h1,l1,h2,l2,h3,l3;
    split_bf(v.x,h0,l0); split_bf(v.y,h1,l1); split_bf(v.z,h2,l2); split_bf(v.w,h3,l3);
    size_t o2 = (size_t)row * (DIMF/2) + lane * 2;
    ((__nv_bfloat162*)fhi)[o2]   = __nv_bfloat162(h0,h1);
    ((__nv_bfloat162*)fhi)[o2+1] = __nv_bfloat162(h2,h3);
    ((__nv_bfloat162*)flo)[o2]   = __nv_bfloat162(l0,l1);
    ((__nv_bfloat162*)flo)[o2+1] = __nv_bfloat162(l2,l3);
}

// ---------------- fused selections: labels_con + pos_sel + neg top-1024 ----------------
__global__ void __launch_bounds__(256) sel_fused(const float* __restrict__ simq,
                                                 const int* __restrict__ labels,
                                                 float* __restrict__ out)
{
    __shared__ uint32_t keys[NEGCNT];
    __shared__ uint32_t buf[KNEG];
    __shared__ int lab[N_SAMP];
    __shared__ int hist[256];
    __shared__ int sh_prefix, sh_target, sh_cnt;
    const int i = blockIdx.x, tid = threadIdx.x;
    const size_t base = (size_t)i * NQS;

    for (int t = tid; t < N_SAMP; t += 256) lab[t] = labels[t];
    if (tid == 0) { sh_target = KNEG; sh_prefix = 0; sh_cnt = 0; }
    __syncthreads();
    const int L = lab[i];

    // labels_con row i
    float* labrow = out + OFF_LABCON + (size_t)i * NCON;
    for (int j = tid; j < 2047; j += 256) {
        int jj = j + (j >= i ? 1 : 0);
        labrow[j] = (L == lab[jj]) ? 1.f : 0.f;
    }
    for (int j = 2047 + tid; j < NCON; j += 256) labrow[j] = (j < 2051) ? 1.f : 0.f;

    // pos_sel: 4 smallest of 8 (ascending)
    if (tid == 0) {
        float v[8];
        #pragma unroll
        for (int k = 0; k < 8; k++) v[k] = simq[base + L * 8 + k];
        #pragma unroll
        for (int a = 1; a < 8; a++) {
            float x = v[a]; int bb = a - 1;
            while (bb >= 0 && v[bb] > x) { v[bb + 1] = v[bb]; bb--; }
            v[bb + 1] = x;
        }
        #pragma unroll
        for (int k = 0; k < 4; k++) out[(size_t)i * NCON + 2047 + k] = v[k];
    }

    // neg keys (order-preserving uint transform)
    for (int t = tid; t < NEGCNT; t += 256) {
        int col = (t < 8 * L) ? t : t + 8;
        uint32_t b = __float_as_uint(simq[base + col]);
        keys[t] = (b >> 31) ? ~b : (b | 0x80000000u);
    }
    __syncthreads();

    uint32_t prefix = 0;
    #pragma unroll
    for (int pass = 0; pass < 4; pass++) {
        const int shift = 24 - pass * 8;
        hist[tid] = 0;
        __syncthreads();
        for (int t = tid; t < NEGCNT; t += 256) {
            uint32_t u = keys[t];
            bool ok = (pass == 0) || ((u >> (shift + 8)) == prefix);
            if (ok) atomicAdd(&hist[(u >> shift) & 255], 1);
        }
        __syncthreads();
        if (tid == 0) {
            int need = sh_target, acc = 0, b = 255;
            while (acc + hist[b] < need) { acc += hist[b]; b--; }
            sh_prefix = (int)((prefix << 8) | (uint32_t)b);
            sh_target = need - acc;
        }
        __syncthreads();
        prefix = (uint32_t)sh_prefix;
    }
    const uint32_t T = prefix;
    const int G = KNEG - sh_target;
    __syncthreads();

    for (int t = tid; t < NEGCNT; t += 256) {
        uint32_t u = keys[t];
        if (u > T) { int p = atomicAdd(&sh_cnt, 1); buf[p] = u; }
    }
    __syncthreads();
    for (int p = G + tid; p < KNEG; p += 256) buf[p] = T;
    __syncthreads();

    for (int k = 2; k <= KNEG; k <<= 1) {
        for (int j = k >> 1; j > 0; j >>= 1) {
            #pragma unroll
            for (int q = 0; q < 4; q++) {
                int t = tid + q * 256;
                int ixj = t ^ j;
                if (ixj > t) {
                    uint32_t a = buf[t], b = buf[ixj];
                    bool up = ((t & k) == 0);
                    if (up ? (a < b) : (a > b)) { buf[t] = b; buf[ixj] = a; }
                }
            }
            __syncthreads();
        }
    }
    #pragma unroll
    for (int q = 0; q < 4; q++) {
        int t = tid + q * 256;
        uint32_t u = buf[t];
        uint32_t bits = (u & 0x80000000u) ? (u & 0x7fffffffu) : ~u;
        out[(size_t)i * NCON + 2051 + t] = __uint_as_float(bits);
    }
}

// ---------------- queue: parallel rank-based update ----------------
__global__ void __launch_bounds__(1024) qprep(const int* __restrict__ labels,
                                              const int* __restrict__ qptr,
                                              int* __restrict__ win, float* __restrict__ outp)
{
    __shared__ int lab[1024];
    __shared__ int cnt[CC];
    const int tid = threadIdx.x;
    lab[tid] = labels[tid];
    if (tid < CC) cnt[tid] = 0;
    __syncthreads();
    const int L = lab[tid];
    atomicAdd(&cnt[L], 1);
    int rank = 0;
    for (int j = 0; j < 1024; j++)
        if (j < tid && lab[j] == L) rank++;
    __syncthreads();
    const int tot = cnt[L];
    int slot = -1;
    if (rank >= tot - 8) slot = L * QQ + ((qptr[L] + rank) & (QQ - 1));
    win[tid] = slot;
    if (tid < CC) outp[tid] = (float)((qptr[tid] + cnt[tid]) & (QQ - 1));
}

__global__ void qcopy(const float* __restrict__ src, float* __restrict__ dst)
{
    int t = blockIdx.x * 256 + threadIdx.x;
    if (t < DIMF * NQ) dst[t] = src[t];
}

__global__ void qwrite(const float* __restrict__ feat, const int* __restrict__ win,
                       float* __restrict__ outq)
{
    int s = win[blockIdx.x];
    if (s < 0) return;
    outq[(size_t)threadIdx.x * NQ + s] = feat[(size_t)blockIdx.x * DIMF + threadIdx.x];
}

// ---------------- launch ----------------
extern "C" void kernel_launch(void* const* d_in, const int* in_sizes, int n_in,
                              void* d_out, int out_size)
{
    const float* img    = (const float*)d_in[0];
    const int*   labels = (const int*)  d_in[1];
    const float* qlist  = (const float*)d_in[2];
    const int*   qptr   = (const int*)  d_in[3];
    const float* enc_W  = (const float*)d_in[6];
    const float* enc_b  = (const float*)d_in[7];
    const float* W1     = (const float*)d_in[8];
    const float* b1     = (const float*)d_in[9];
    const float* gamma  = (const float*)d_in[10];
    const float* beta   = (const float*)d_in[11];
    const float* W2     = (const float*)d_in[12];
    const float* b2     = (const float*)d_in[13];
    const float* linW   = (const float*)d_in[14];
    const float* linb   = (const float*)d_in[15];
    float* out = (float*)d_out;

    float *h, *feat, *simq, *fpart; int* win;
    __nv_bfloat16 *ahi, *alo, *chi, *clo, *fhi, *flo;
    __nv_bfloat16 *ehi, *elo, *w1hi, *w1lo, *lnhi, *lnlo, *w2hi, *w2lo, *qhi, *qlo;
    cudaGetSymbolAddress((void**)&h,     g_h);
    cudaGetSymbolAddress((void**)&feat,  g_feat);
    cudaGetSymbolAddress((void**)&simq,  g_simq);
    cudaGetSymbolAddress((void**)&fpart, g_fpart);
    cudaGetSymbolAddress((void**)&win,   g_win);
    cudaGetSymbolAddress((void**)&ahi,   g_ahi);
    cudaGetSymbolAddress((void**)&alo,   g_alo);
    cudaGetSymbolAddress((void**)&chi,   g_chi);
    cudaGetSymbolAddress((void**)&clo,   g_clo);
    cudaGetSymbolAddress((void**)&fhi,   g_fhi);
    cudaGetSymbolAddress((void**)&flo,   g_flo);
    cudaGetSymbolAddress((void**)&ehi,   g_ehi);
    cudaGetSymbolAddress((void**)&elo,   g_elo);
    cudaGetSymbolAddress((void**)&w1hi,  g_w1hi);
    cudaGetSymbolAddress((void**)&w1lo,  g_w1lo);
    cudaGetSymbolAddress((void**)&lnhi,  g_lnhi);
    cudaGetSymbolAddress((void**)&lnlo,  g_lnlo);
    cudaGetSymbolAddress((void**)&w2hi,  g_w2hi);
    cudaGetSymbolAddress((void**)&w2lo,  g_w2lo);
    cudaGetSymbolAddress((void**)&qhi,   g_qhi);
    cudaGetSymbolAddress((void**)&qlo,   g_qlo);

    cudaFuncSetAttribute(gemm_mma<8>, cudaFuncAttributeMaxDynamicSharedMemorySize, 122880);
    cudaFuncSetAttribute(gemm_mma<4>, cudaFuncAttributeMaxDynamicSharedMemorySize, 81920);

    // all weight conversions + img split
    conv_all<<<9472, 256>>>(enc_W, W1, linW, W2, qlist,
                            ehi, elo, w1hi, w1lo, lnhi, lnlo, w2hi, w2lo, qhi, qlo);
    conv_plain<<<(N_SAMP * DIN / 4 + 255) / 256, 256>>>(img, chi, clo, N_SAMP * DIN / 4);

    // mid(split) = img @ enc_W + enc_b
    gemm_mma<8><<<dim3(8, 16), 512, 122880>>>(chi, clo, ehi, elo, enc_b, nullptr, ahi, alo,
                                              DIN, DIN, DFEAT, 3, 0);
    // h = mid @ W1 + b1 ; logit = mid @ linW + linb
    gemm_mma<8><<<dim3(8, 16), 512, 122880>>>(ahi, alo, w1hi, w1lo, b1, h, nullptr, nullptr,
                                              DFEAT, DFEAT, DFEAT, 0, 0);
    gemm_mma<4><<<dim3(8, 16), 512, 81920>>>(ahi, alo, lnhi, lnlo, linb, out + OFF_LOGIT, nullptr, nullptr,
                                             DFEAT, DFEAT, CC, 2, CC);
    // batchnorm + relu -> hn split
    bn_partial<<<dim3(DFEAT / 256, 16), 256>>>(h);
    bn_final<<<DFEAT / 256, 256>>>();
    bn_apply<<<(N_SAMP * DFEAT / 2) / 256, 256>>>(h, gamma, beta, chi, clo);
    // feat = hn @ W2 + b2 (split-K=4), then fused norm+split
    gemm_mma<4><<<dim3(1, 16, 4), 512, 81920>>>(chi, clo, w2hi, w2lo, nullptr, fpart, nullptr, nullptr,
                                                DFEAT, DFEAT / 4, DIMF, 4, 0);
    feat_fix<<<N_SAMP / 8, 256>>>(fpart, b2, feat, fhi, flo);
    // sim_b off-diagonal
    gemm_mma<8><<<dim3(8, 16), 512, 122880>>>(fhi, flo, fhi, flo, nullptr, out + OFF_SIMCON, nullptr, nullptr,
                                              DIMF, DIMF, NCON, 1, 0);
    // sim_q
    gemm_mma<8><<<dim3(32, 16), 512, 122880>>>(fhi, flo, qhi, qlo, nullptr, simq, nullptr, nullptr,
                                               DIMF, DIMF, NQS, 0, 0);
    // fused selections (labcon + pos + neg)
    sel_fused<<<N_SAMP, 256>>>(simq, labels, out);
    // queue update (parallel)
    qprep<<<1, 1024>>>(labels, qptr, win, out + OFF_QPTR);
    qcopy<<<(DIMF * NQ + 255) / 256, 256>>>(qlist, out + OFF_QUEUE);
    qwrite<<<1024, 128>>>(feat, win, out + OFF_QUEUE);
}

// round 10
// speedup vs baseline: 1.0702x; 1.0702x over previous
#include <cuda_runtime.h>
#include <cuda_bf16.h>
#include <cstdint>

#define N_SAMP 2048
#define DIN    1024
#define DFEAT  2048
#define DIMF   128
#define CC     1000
#define QQ     8
#define NQ     8000
#define NQS    8192      // padded sim_q stride
#define KNEG   1024
#define NCON   3075      // 2047 + 4 + 1024
#define NEGCNT 7992

// output layout (float32, tuple order, row-major flattened)
#define OFF_SIMCON 0ull
#define OFF_LABCON 6297600ull
#define OFF_LOGIT  12595200ull
#define OFF_QUEUE  14643200ull
#define OFF_QPTR   15667200ull

// ---------------- device scratch ----------------
__device__ float g_h   [N_SAMP * DFEAT];
__device__ float g_simq[N_SAMP * NQS];
__device__ float g_feat[N_SAMP * DIMF];
__device__ float g_fpart[4 * N_SAMP * DIMF];
__device__ float g_psum[16 * DFEAT];
__device__ float g_psq [16 * DFEAT];
__device__ float g_mean[DFEAT];
__device__ float g_rstd[DFEAT];
__device__ int   g_win [1024];
__device__ __nv_bfloat16 g_ahi[N_SAMP * DFEAT];   // mid split
__device__ __nv_bfloat16 g_alo[N_SAMP * DFEAT];
__device__ __nv_bfloat16 g_chi[N_SAMP * DFEAT];   // img split, then hn split
__device__ __nv_bfloat16 g_clo[N_SAMP * DFEAT];
__device__ __nv_bfloat16 g_fhi[N_SAMP * DIMF];    // feat split
__device__ __nv_bfloat16 g_flo[N_SAMP * DIMF];
// weight splits (transposed [N][K])
__device__ __nv_bfloat16 g_ehi [DFEAT * DIN];
__device__ __nv_bfloat16 g_elo [DFEAT * DIN];
__device__ __nv_bfloat16 g_w1hi[DFEAT * DFEAT];
__device__ __nv_bfloat16 g_w1lo[DFEAT * DFEAT];
__device__ __nv_bfloat16 g_lnhi[1024 * DFEAT];
__device__ __nv_bfloat16 g_lnlo[1024 * DFEAT];
__device__ __nv_bfloat16 g_w2hi[DIMF * DFEAT];
__device__ __nv_bfloat16 g_w2lo[DIMF * DFEAT];
__device__ __nv_bfloat16 g_qhi [NQS * DIMF];
__device__ __nv_bfloat16 g_qlo [NQS * DIMF];

// ================= helpers =================
__device__ __forceinline__ uint32_t smem_u32(const void* p) {
    uint32_t a;
    asm("{ .reg .u64 t; cvta.to.shared.u64 t, %1; cvt.u32.u64 %0, t; }" : "=r"(a) : "l"(p));
    return a;
}
__device__ __forceinline__ void cpa16(uint32_t s, const void* g) {
    asm volatile("cp.async.cg.shared.global [%0], [%1], 16;" :: "r"(s), "l"(g) : "memory");
}
__device__ __forceinline__ void ldsm4(uint32_t* r, uint32_t addr) {
    asm volatile("ldmatrix.sync.aligned.m8n8.x4.shared.b16 {%0,%1,%2,%3}, [%4];"
                 : "=r"(r[0]), "=r"(r[1]), "=r"(r[2]), "=r"(r[3]) : "r"(addr));
}
__device__ __forceinline__ void mma_bf16(float* c, const uint32_t* a, const uint32_t* b) {
    asm volatile("mma.sync.aligned.m16n8k16.row.col.f32.bf16.bf16.f32 "
                 "{%0,%1,%2,%3}, {%4,%5,%6,%7}, {%8,%9}, {%0,%1,%2,%3};"
                 : "+f"(c[0]), "+f"(c[1]), "+f"(c[2]), "+f"(c[3])
                 : "r"(a[0]), "r"(a[1]), "r"(a[2]), "r"(a[3]), "r"(b[0]), "r"(b[1]));
}
__device__ __forceinline__ void split_bf(float v, __nv_bfloat16& h, __nv_bfloat16& l) {
    h = __float2bfloat16(v);
    l = __float2bfloat16(v - __bfloat162float(h));
}

// ================= split-bf16 MMA GEMM (identical to R9) =================
template<int NI>
__global__ void __launch_bounds__(512, 1) gemm_mma(
    const __nv_bfloat16* __restrict__ Ahi, const __nv_bfloat16* __restrict__ Alo,
    const __nv_bfloat16* __restrict__ Bhi, const __nv_bfloat16* __restrict__ Blo,
    const float* __restrict__ bias, float* __restrict__ C,
    __nv_bfloat16* __restrict__ Ohi, __nv_bfloat16* __restrict__ Olo,
    int K, int Ksub, int ldC, int mode, int nbound)
{
    constexpr uint32_t SA_LO = 10240;
    constexpr uint32_t SB_HI = 20480;
    constexpr uint32_t SB_LO = 20480 + NI * 2560;
    constexpr uint32_t STAGE = 20480 + 2 * NI * 2560;

    extern __shared__ __align__(128) char sm[];
    const uint32_t sb = smem_u32(sm);
    const int tid = threadIdx.x, wid = tid >> 5, lane = tid & 31;
    const int rowBase = blockIdx.y * 128, nBase = blockIdx.x * (NI * 32);
    const int kbase = blockIdx.z * Ksub;
    const int nch = Ksub >> 5;

    float acc[2][NI][4];
    #pragma unroll
    for (int i = 0; i < 2; i++)
        #pragma unroll
        for (int j = 0; j < NI; j++)
            #pragma unroll
            for (int q = 0; q < 4; q++) acc[i][j][q] = 0.f;

    const uint32_t aoff = (tid >> 2) * 80 + (tid & 3) * 16;
    const size_t ga = (size_t)(rowBase + (tid >> 2)) * K + (tid & 3) * 8 + kbase;
    const size_t gb = (size_t)(nBase  + (tid >> 2)) * K + (tid & 3) * 8 + kbase;

#define ISSUE(st, ch) do {                                                            \
        const int k0_ = (ch) << 5;                                                    \
        const uint32_t B0_ = sb + (st) * STAGE;                                       \
        cpa16(B0_ + aoff,         Ahi + ga + k0_);                                    \
        cpa16(B0_ + SA_LO + aoff, Alo + ga + k0_);                                    \
        _Pragma("unroll")                                                             \
        for (int it = 0; it < NI / 4; it++) {                                         \
            cpa16(B0_ + SB_HI + aoff + it * 10240, Bhi + gb + (size_t)(it*128)*K + k0_); \
            cpa16(B0_ + SB_LO + aoff + it * 10240, Blo + gb + (size_t)(it*128)*K + k0_); \
        }                                                                             \
        asm volatile("cp.async.commit_group;" ::: "memory");                          \
    } while (0)

    ISSUE(0, 0);

    const int wm = (wid >> 2) * 32, wn = (wid & 3) * (NI * 8);
    const int arow = lane & 15, ahalf = lane >> 4;
    const int bpr = ((lane >> 4) & 1) * 8 + (lane & 7);
    const int bkh = (lane >> 3) & 1;

    for (int ch = 0; ch < nch; ch++) {
        if (ch + 1 < nch) {
            ISSUE((ch + 1) & 1, ch + 1);
            asm volatile("cp.async.wait_group 1;" ::: "memory");
        } else {
            asm volatile("cp.async.wait_group 0;" ::: "memory");
        }
        __syncthreads();
        const uint32_t base = sb + (ch & 1) * STAGE;

        #pragma unroll
        for (int ks = 0; ks < 2; ks++) {
            uint32_t fahi[2][4], falo[2][4];
            #pragma unroll
            for (int mi = 0; mi < 2; mi++) {
                uint32_t ad = base + (wm + mi * 16 + arow) * 80 + ks * 32 + ahalf * 16;
                ldsm4(fahi[mi], ad);
                ldsm4(falo[mi], ad + SA_LO);
            }
            #pragma unroll
            for (int p = 0; p < NI / 2; p++) {
                uint32_t bd = base + SB_HI + (wn + p * 16 + bpr) * 80 + ks * 32 + bkh * 16;
                uint32_t fbh[4], fbl[4];
                ldsm4(fbh, bd);
                ldsm4(fbl, bd + NI * 2560);
                #pragma unroll
                for (int mi = 0; mi < 2; mi++) {
                    mma_bf16(acc[mi][2*p],   fahi[mi], fbh);
                    mma_bf16(acc[mi][2*p+1], fahi[mi], fbh + 2);
                }
                #pragma unroll
                for (int mi = 0; mi < 2; mi++) {
                    mma_bf16(acc[mi][2*p],   fahi[mi], fbl);
                    mma_bf16(acc[mi][2*p+1], fahi[mi], fbl + 2);
                }
                #pragma unroll
                for (int mi = 0; mi < 2; mi++) {
                    mma_bf16(acc[mi][2*p],   falo[mi], fbh);
                    mma_bf16(acc[mi][2*p+1], falo[mi], fbh + 2);
                }
            }
        }
        __syncthreads();
    }
#undef ISSUE

    const int qrow = lane >> 2, qcol = (lane & 3) * 2;
    #pragma unroll
    for (int mi = 0; mi < 2; mi++) {
        #pragma unroll
        for (int hh = 0; hh < 2; hh++) {
            const int r = rowBase + wm + mi * 16 + qrow + hh * 8;
            #pragma unroll
            for (int ni = 0; ni < NI; ni++) {
                const int c = nBase + wn + ni * 8 + qcol;
                float v0 = acc[mi][ni][hh * 2 + 0];
                float v1 = acc[mi][ni][hh * 2 + 1];
                if (mode == 0) {
                    if (bias) { v0 += bias[c]; v1 += bias[c + 1]; }
                    *(float2*)(C + (size_t)r * ldC + c) = make_float2(v0, v1);
                } else if (mode == 1) {
                    if (c != r)     C[(size_t)r * ldC + c     - (c     > r ? 1 : 0)] = v0;
                    if (c + 1 != r) C[(size_t)r * ldC + c + 1 - (c + 1 > r ? 1 : 0)] = v1;
                } else if (mode == 2) {
                    if (c < nbound)     C[(size_t)r * ldC + c]     = v0 + bias[c];
                    if (c + 1 < nbound) C[(size_t)r * ldC + c + 1] = v1 + bias[c + 1];
                } else if (mode == 3) {
                    v0 += bias[c]; v1 += bias[c + 1];
                    __nv_bfloat16 h0, l0, h1, l1;
                    split_bf(v0, h0, l0); split_bf(v1, h1, l1);
                    *(__nv_bfloat162*)(Ohi + (size_t)r * ldC + c) = __nv_bfloat162(h0, h1);
                    *(__nv_bfloat162*)(Olo + (size_t)r * ldC + c) = __nv_bfloat162(l0, l1);
                } else {
                    float* Cz = C + (size_t)blockIdx.z * N_SAMP * DIMF;
                    *(float2*)(Cz + (size_t)r * ldC + c) = make_float2(v0, v1);
                }
            }
        }
    }
}

// ============ all weight conversions in one kernel ============
__global__ void conv_all(const float* __restrict__ encW, const float* __restrict__ W1,
                         const float* __restrict__ linW, const float* __restrict__ W2,
                         const float* __restrict__ ql,
                         __nv_bfloat16* ehi, __nv_bfloat16* elo,
                         __nv_bfloat16* w1hi, __nv_bfloat16* w1lo,
                         __nv_bfloat16* lnhi, __nv_bfloat16* lnlo,
                         __nv_bfloat16* w2hi, __nv_bfloat16* w2lo,
                         __nv_bfloat16* qhi,  __nv_bfloat16* qlo)
{
    __shared__ float ts[32][33];
    const int b = blockIdx.x;
    const float* W; __nv_bfloat16 *hi, *lo; int K, N, nx, id;
    if (b < 2048)      { W = encW; hi = ehi;  lo = elo;  K = 1024; N = 2048; nx = 64;  id = b; }
    else if (b < 6144) { W = W1;   hi = w1hi; lo = w1lo; K = 2048; N = 2048; nx = 64;  id = b - 2048; }
    else if (b < 8192) { W = linW; hi = lnhi; lo = lnlo; K = 2048; N = 1000; nx = 32;  id = b - 6144; }
    else if (b < 8448) { W = W2;   hi = w2hi; lo = w2lo; K = 2048; N = 128;  nx = 4;   id = b - 8192; }
    else               { W = ql;   hi = qhi;  lo = qlo;  K = 128;  N = 8000; nx = 256; id = b - 8448; }
    const int nb = (id % nx) * 32, kb = (id / nx) * 32;

    const int c = threadIdx.x & 31, r8 = threadIdx.x >> 5;
    #pragma unroll
    for (int rr = r8; rr < 32; rr += 8) {
        int n = nb + c;
        ts[rr][c] = (n < N) ? W[(size_t)(kb + rr) * N + n] : 0.f;
    }
    __syncthreads();
    const int c16 = threadIdx.x & 15, rh = threadIdx.x >> 4;
    #pragma unroll
    for (int rr = rh; rr < 32; rr += 16) {
        float v0 = ts[2 * c16][rr], v1 = ts[2 * c16 + 1][rr];
        __nv_bfloat16 h0, l0, h1, l1;
        split_bf(v0, h0, l0); split_bf(v1, h1, l1);
        size_t o = (size_t)(nb + rr) * K + kb;
        ((__nv_bfloat162*)(hi + o))[c16] = __nv_bfloat162(h0, h1);
        ((__nv_bfloat162*)(lo + o))[c16] = __nv_bfloat162(l0, l1);
    }
}

__global__ void conv_plain(const float* __restrict__ X, __nv_bfloat16* __restrict__ hi,
                           __nv_bfloat16* __restrict__ lo, int n4)
{
    int i = blockIdx.x * 256 + threadIdx.x;
    if (i >= n4) return;
    float4 v = ((const float4*)X)[i];
    __nv_bfloat16 h0,l0,h1,l1,h2,l2,h3,l3;
    split_bf(v.x,h0,l0); split_bf(v.y,h1,l1); split_bf(v.z,h2,l2); split_bf(v.w,h3,l3);
    ((__nv_bfloat162*)hi)[i*2]   = __nv_bfloat162(h0,h1);
    ((__nv_bfloat162*)hi)[i*2+1] = __nv_bfloat162(h2,h3);
    ((__nv_bfloat162*)lo)[i*2]   = __nv_bfloat162(l0,l1);
    ((__nv_bfloat162*)lo)[i*2+1] = __nv_bfloat162(l2,l3);
}

// ---------------- batchnorm ----------------
__global__ void bn_partial(const float* __restrict__ h)
{
    int col = blockIdx.x * 256 + threadIdx.x;
    int r0 = blockIdx.y * 128;
    float s = 0.f, sq = 0.f;
    for (int i = 0; i < 128; i++) {
        float v = h[(size_t)(r0 + i) * DFEAT + col];
        s += v; sq += v * v;
    }
    g_psum[blockIdx.y * DFEAT + col] = s;
    g_psq [blockIdx.y * DFEAT + col] = sq;
}

__global__ void bn_final()
{
    int col = blockIdx.x * 256 + threadIdx.x;
    float s = 0.f, sq = 0.f;
    for (int i = 0; i < 16; i++) { s += g_psum[i * DFEAT + col]; sq += g_psq[i * DFEAT + col]; }
    float mean = s * (1.f / N_SAMP);
    float var  = sq * (1.f / N_SAMP) - mean * mean;
    g_mean[col] = mean;
    g_rstd[col] = rsqrtf(var + 1e-5f);
}

__global__ void bn_apply(const float* __restrict__ h, const float* __restrict__ gamma,
                         const float* __restrict__ beta,
                         __nv_bfloat16* __restrict__ hi, __nv_bfloat16* __restrict__ lo)
{
    int idx = blockIdx.x * 256 + threadIdx.x;
    int col = (idx * 2) & (DFEAT - 1);
    float2 v2 = ((const float2*)h)[idx];
    float v0 = (v2.x - g_mean[col])   * g_rstd[col]   * gamma[col]   + beta[col];
    float v1 = (v2.y - g_mean[col+1]) * g_rstd[col+1] * gamma[col+1] + beta[col+1];
    v0 = v0 > 0.f ? v0 : 0.f;
    v1 = v1 > 0.f ? v1 : 0.f;
    __nv_bfloat16 h0,l0,h1,l1;
    split_bf(v0,h0,l0); split_bf(v1,h1,l1);
    ((__nv_bfloat162*)hi)[idx] = __nv_bfloat162(h0,h1);
    ((__nv_bfloat162*)lo)[idx] = __nv_bfloat162(l0,l1);
}

// ---------------- feat finalize ----------------
__global__ void feat_fix(const float* __restrict__ part, const float* __restrict__ b2,
                         float* __restrict__ feat,
                         __nv_bfloat16* __restrict__ fhi, __nv_bfloat16* __restrict__ flo)
{
    int w = threadIdx.x >> 5, lane = threadIdx.x & 31;
    int row = blockIdx.x * 8 + w;
    float4 v = make_float4(0.f, 0.f, 0.f, 0.f);
    #pragma unroll
    for (int p = 0; p < 4; p++) {
        float4 t = *(const float4*)(part + (size_t)p * N_SAMP * DIMF + (size_t)row * DIMF + lane * 4);
        v.x += t.x; v.y += t.y; v.z += t.z; v.w += t.w;
    }
    float4 b = *(const float4*)(b2 + lane * 4);
    v.x += b.x; v.y += b.y; v.z += b.z; v.w += b.w;
    float ss = v.x * v.x + v.y * v.y + v.z * v.z + v.w * v.w;
    #pragma unroll
    for (int o = 16; o; o >>= 1) ss += __shfl_xor_sync(0xffffffffu, ss, o);
    float r = rsqrtf(ss);
    v.x *= r; v.y *= r; v.z *= r; v.w *= r;
    *(float4*)(feat + (size_t)row * DIMF + lane * 4) = v;
    __nv_bfloat16 h0,l0,h1,l1,h2,l2,h3,l3;
    split_bf(v.x,h0,l0); split_bf(v.y,h1,l1); split_bf(v.z,h2,l2); split_bf(v.w,h3,l3);
    size_t o2 = (size_t)row * (DIMF/2) + lane * 2;
    ((__nv_bfloat162*)fhi)[o2]   = __nv_bfloat162(h0,h1);
    ((__nv_bfloat162*)fhi)[o2+1] = __nv_bfloat162(h2,h3);
    ((__nv_bfloat162*)flo)[o2]   = __nv_bfloat162(l0,l1);
    ((__nv_bfloat162*)flo)[o2+1] = __nv_bfloat162(l2,l3);
}

// ---------------- fused selections ----------------
__global__ void __launch_bounds__(256) sel_fused(const float* __restrict__ simq,
                                                 const int* __restrict__ labels,
                                                 float* __restrict__ out)
{
    __shared__ uint32_t keys[NEGCNT];
    __shared__ uint32_t buf[KNEG];
    __shared__ int lab[N_SAMP];
    __shared__ int hist[256];
    __shared__ int sh_prefix, sh_target, sh_cnt;
    const int i = blockIdx.x, tid = threadIdx.x;
    const size_t base = (size_t)i * NQS;

    for (int t = tid; t < N_SAMP; t += 256) lab[t] = labels[t];
    if (tid == 0) { sh_target = KNEG; sh_prefix = 0; sh_cnt = 0; }
    __syncthreads();
    const int L = lab[i];

    float* labrow = out + OFF_LABCON + (size_t)i * NCON;
    for (int j = tid; j < 2047; j += 256) {
        int jj = j + (j >= i ? 1 : 0);
        labrow[j] = (L == lab[jj]) ? 1.f : 0.f;
    }
    for (int j = 2047 + tid; j < NCON; j += 256) labrow[j] = (j < 2051) ? 1.f : 0.f;

    if (tid == 0) {
        float v[8];
        #pragma unroll
        for (int k = 0; k < 8; k++) v[k] = simq[base + L * 8 + k];
        #pragma unroll
        for (int a = 1; a < 8; a++) {
            float x = v[a]; int bb = a - 1;
            while (bb >= 0 && v[bb] > x) { v[bb + 1] = v[bb]; bb--; }
            v[bb + 1] = x;
        }
        #pragma unroll
        for (int k = 0; k < 4; k++) out[(size_t)i * NCON + 2047 + k] = v[k];
    }

    for (int t = tid; t < NEGCNT; t += 256) {
        int col = (t < 8 * L) ? t : t + 8;
        uint32_t b = __float_as_uint(simq[base + col]);
        keys[t] = (b >> 31) ? ~b : (b | 0x80000000u);
    }
    __syncthreads();

    uint32_t prefix = 0;
    #pragma unroll
    for (int pass = 0; pass < 4; pass++) {
        const int shift = 24 - pass * 8;
        hist[tid] = 0;
        __syncthreads();
        for (int t = tid; t < NEGCNT; t += 256) {
            uint32_t u = keys[t];
            bool ok = (pass == 0) || ((u >> (shift + 8)) == prefix);
            if (ok) atomicAdd(&hist[(u >> shift) & 255], 1);
        }
        __syncthreads();
        if (tid == 0) {
            int need = sh_target, acc = 0, b = 255;
            while (acc + hist[b] < need) { acc += hist[b]; b--; }
            sh_prefix = (int)((prefix << 8) | (uint32_t)b);
            sh_target = need - acc;
        }
        __syncthreads();
        prefix = (uint32_t)sh_prefix;
    }
    const uint32_t T = prefix;
    const int G = KNEG - sh_target;
    __syncthreads();

    for (int t = tid; t < NEGCNT; t += 256) {
        uint32_t u = keys[t];
        if (u > T) { int p = atomicAdd(&sh_cnt, 1); buf[p] = u; }
    }
    __syncthreads();
    for (int p = G + tid; p < KNEG; p += 256) buf[p] = T;
    __syncthreads();

    for (int k = 2; k <= KNEG; k <<= 1) {
        for (int j = k >> 1; j > 0; j >>= 1) {
            #pragma unroll
            for (int q = 0; q < 4; q++) {
                int t = tid + q * 256;
                int ixj = t ^ j;
                if (ixj > t) {
                    uint32_t a = buf[t], b = buf[ixj];
                    bool up = ((t & k) == 0);
                    if (up ? (a < b) : (a > b)) { buf[t] = b; buf[ixj] = a; }
                }
            }
            __syncthreads();
        }
    }
    #pragma unroll
    for (int q = 0; q < 4; q++) {
        int t = tid + q * 256;
        uint32_t u = buf[t];
        uint32_t bits = (u & 0x80000000u) ? (u & 0x7fffffffu) : ~u;
        out[(size_t)i * NCON + 2051 + t] = __uint_as_float(bits);
    }
}

// ---------------- queue: parallel rank-based update ----------------
__global__ void __launch_bounds__(1024) qprep(const int* __restrict__ labels,
                                              const int* __restrict__ qptr,
                                              int* __restrict__ win, float* __restrict__ outp)
{
    __shared__ int lab[1024];
    __shared__ int cnt[CC];
    const int tid = threadIdx.x;
    lab[tid] = labels[tid];
    if (tid < CC) cnt[tid] = 0;
    __syncthreads();
    const int L = lab[tid];
    atomicAdd(&cnt[L], 1);
    int rank = 0;
    for (int j = 0; j < 1024; j++)
        if (j < tid && lab[j] == L) rank++;
    __syncthreads();
    const int tot = cnt[L];
    int slot = -1;
    if (rank >= tot - 8) slot = L * QQ + ((qptr[L] + rank) & (QQ - 1));
    win[tid] = slot;
    if (tid < CC) outp[tid] = (float)((qptr[tid] + cnt[tid]) & (QQ - 1));
}

__global__ void qcopy(const float* __restrict__ src, float* __restrict__ dst)
{
    int t = blockIdx.x * 256 + threadIdx.x;
    if (t < DIMF * NQ) dst[t] = src[t];
}

__global__ void qwrite(const float* __restrict__ feat, const int* __restrict__ win,
                       float* __restrict__ outq)
{
    int s = win[blockIdx.x];
    if (s < 0) return;
    outq[(size_t)threadIdx.x * NQ + s] = feat[(size_t)blockIdx.x * DIMF + threadIdx.x];
}

// ---------------- launch (stream fork/join inside graph capture) ----------------
extern "C" void kernel_launch(void* const* d_in, const int* in_sizes, int n_in,
                              void* d_out, int out_size)
{
    const float* img    = (const float*)d_in[0];
    const int*   labels = (const int*)  d_in[1];
    const float* qlist  = (const float*)d_in[2];
    const int*   qptr   = (const int*)  d_in[3];
    const float* enc_W  = (const float*)d_in[6];
    const float* enc_b  = (const float*)d_in[7];
    const float* W1     = (const float*)d_in[8];
    const float* b1     = (const float*)d_in[9];
    const float* gamma  = (const float*)d_in[10];
    const float* beta   = (const float*)d_in[11];
    const float* W2     = (const float*)d_in[12];
    const float* b2     = (const float*)d_in[13];
    const float* linW   = (const float*)d_in[14];
    const float* linb   = (const float*)d_in[15];
    float* out = (float*)d_out;

    float *h, *feat, *simq, *fpart; int* win;
    __nv_bfloat16 *ahi, *alo, *chi, *clo, *fhi, *flo;
    __nv_bfloat16 *ehi, *elo, *w1hi, *w1lo, *lnhi, *lnlo, *w2hi, *w2lo, *qhi, *qlo;
    cudaGetSymbolAddress((void**)&h,     g_h);
    cudaGetSymbolAddress((void**)&feat,  g_feat);
    cudaGetSymbolAddress((void**)&simq,  g_simq);
    cudaGetSymbolAddress((void**)&fpart, g_fpart);
    cudaGetSymbolAddress((void**)&win,   g_win);
    cudaGetSymbolAddress((void**)&ahi,   g_ahi);
    cudaGetSymbolAddress((void**)&alo,   g_alo);
    cudaGetSymbolAddress((void**)&chi,   g_chi);
    cudaGetSymbolAddress((void**)&clo,   g_clo);
    cudaGetSymbolAddress((void**)&fhi,   g_fhi);
    cudaGetSymbolAddress((void**)&flo,   g_flo);
    cudaGetSymbolAddress((void**)&ehi,   g_ehi);
    cudaGetSymbolAddress((void**)&elo,   g_elo);
    cudaGetSymbolAddress((void**)&w1hi,  g_w1hi);
    cudaGetSymbolAddress((void**)&w1lo,  g_w1lo);
    cudaGetSymbolAddress((void**)&lnhi,  g_lnhi);
    cudaGetSymbolAddress((void**)&lnlo,  g_lnlo);
    cudaGetSymbolAddress((void**)&w2hi,  g_w2hi);
    cudaGetSymbolAddress((void**)&w2lo,  g_w2lo);
    cudaGetSymbolAddress((void**)&qhi,   g_qhi);
    cudaGetSymbolAddress((void**)&qlo,   g_qlo);

    cudaFuncSetAttribute(gemm_mma<8>, cudaFuncAttributeMaxDynamicSharedMemorySize, 122880);
    cudaFuncSetAttribute(gemm_mma<4>, cudaFuncAttributeMaxDynamicSharedMemorySize, 81920);

    cudaStream_t s1, s2;
    cudaStreamCreateWithFlags(&s1, cudaStreamNonBlocking);
    cudaStreamCreateWithFlags(&s2, cudaStreamNonBlocking);
    cudaEvent_t eRoot, eMid, eFeat, eLogit, eSb, eQ;
    cudaEventCreateWithFlags(&eRoot,  cudaEventDisableTiming);
    cudaEventCreateWithFlags(&eMid,   cudaEventDisableTiming);
    cudaEventCreateWithFlags(&eFeat,  cudaEventDisableTiming);
    cudaEventCreateWithFlags(&eLogit, cudaEventDisableTiming);
    cudaEventCreateWithFlags(&eSb,    cudaEventDisableTiming);
    cudaEventCreateWithFlags(&eQ,     cudaEventDisableTiming);

    // s0: conversions, then enc GEMM
    conv_plain<<<(N_SAMP * DIN / 4 + 255) / 256, 256>>>(img, chi, clo, N_SAMP * DIN / 4);
    conv_all<<<9472, 256>>>(enc_W, W1, linW, W2, qlist,
                            ehi, elo, w1hi, w1lo, lnhi, lnlo, w2hi, w2lo, qhi, qlo);
    cudaEventRecord(eRoot, 0);

    // s1 fork: queue prep path (independent of everything but labels/qptr/qlist)
    cudaStreamWaitEvent(s1, eRoot, 0);
    qprep<<<1, 1024, 0, s1>>>(labels, qptr, win, out + OFF_QPTR);
    qcopy<<<(DIMF * NQ + 255) / 256, 256, 0, s1>>>(qlist, out + OFF_QUEUE);

    // s0: mid(split) = img @ enc_W + enc_b
    gemm_mma<8><<<dim3(8, 16), 512, 122880>>>(chi, clo, ehi, elo, enc_b, nullptr, ahi, alo,
                                              DIN, DIN, DFEAT, 3, 0);
    cudaEventRecord(eMid, 0);

    // s2 fork: logit = mid @ linW + linb (concurrent with W1 + BN chain)
    cudaStreamWaitEvent(s2, eMid, 0);
    gemm_mma<4><<<dim3(8, 16), 512, 81920, s2>>>(ahi, alo, lnhi, lnlo, linb, out + OFF_LOGIT,
                                                 nullptr, nullptr, DFEAT, DFEAT, CC, 2, CC);
    cudaEventRecord(eLogit, s2);

    // s0: h = mid @ W1 + b1 ; batchnorm + relu -> hn split ; feat GEMM ; feat_fix
    gemm_mma<8><<<dim3(8, 16), 512, 122880>>>(ahi, alo, w1hi, w1lo, b1, h, nullptr, nullptr,
                                              DFEAT, DFEAT, DFEAT, 0, 0);
    bn_partial<<<dim3(DFEAT / 256, 16), 256>>>(h);
    bn_final<<<DFEAT / 256, 256>>>();
    bn_apply<<<(N_SAMP * DFEAT / 2) / 256, 256>>>(h, gamma, beta, chi, clo);
    gemm_mma<4><<<dim3(1, 16, 4), 512, 81920>>>(chi, clo, w2hi, w2lo, nullptr, fpart, nullptr, nullptr,
                                                DFEAT, DFEAT / 4, DIMF, 4, 0);
    feat_fix<<<N_SAMP / 8, 256>>>(fpart, b2, feat, fhi, flo);
    cudaEventRecord(eFeat, 0);

    // s2 fork: sim_b off-diagonal (concurrent with sim_q)
    cudaStreamWaitEvent(s2, eFeat, 0);
    gemm_mma<8><<<dim3(8, 16), 512, 122880, s2>>>(fhi, flo, fhi, flo, nullptr, out + OFF_SIMCON,
                                                  nullptr, nullptr, DIMF, DIMF, NCON, 1, 0);
    cudaEventRecord(eSb, s2);

    // s1: qwrite after feat ready (qprep/qcopy already done on s1)
    cudaStreamWaitEvent(s1, eFeat, 0);
    qwrite<<<1024, 128, 0, s1>>>(feat, win, out + OFF_QUEUE);
    cudaEventRecord(eQ, s1);

    // s0: sim_q then fused selections
    gemm_mma<8><<<dim3(32, 16), 512, 122880>>>(fhi, flo, qhi, qlo, nullptr, simq, nullptr, nullptr,
                                               DIMF, DIMF, NQS, 0, 0);
    sel_fused<<<N_SAMP, 256>>>(simq, labels, out);

    // join all side streams back into s0
    cudaStreamWaitEvent(0, eLogit, 0);
    cudaStreamWaitEvent(0, eSb, 0);
    cudaStreamWaitEvent(0, eQ, 0);

    cudaEventDestroy(eRoot); cudaEventDestroy(eMid); cudaEventDestroy(eFeat);
    cudaEventDestroy(eLogit); cudaEventDestroy(eSb); cudaEventDestroy(eQ);
    cudaStreamDestroy(s1); cudaStreamDestroy(s2);
}